// round 5
// baseline (speedup 1.0000x reference)
#include <cuda_runtime.h>
#include <cstdint>

#define NTAGS 24
#define SEQ   512
#define BATCH 2048
#define WPB   4
#define THREADS (WPB * 32)
#define CH    8
#define NCHUNK (SEQ / CH)
#define FULL  0xffffffffu

typedef unsigned long long u64;

__device__ float    g_part[BATCH];
__device__ unsigned g_ctr = 0;

static __device__ __forceinline__ u64 pk2(float lo, float hi) {
    u64 r; asm("mov.b64 %0, {%1, %2};" : "=l"(r) : "f"(lo), "f"(hi)); return r;
}
static __device__ __forceinline__ void un2(u64 v, float& lo, float& hi) {
    asm("mov.b64 {%0, %1}, %2;" : "=f"(lo), "=f"(hi) : "l"(v));
}
static __device__ __forceinline__ u64 fma2(u64 a, u64 b, u64 c) {
    u64 d; asm("fma.rn.f32x2 %0, %1, %2, %3;" : "=l"(d) : "l"(a), "l"(b), "l"(c)); return d;
}
static __device__ __forceinline__ u64 mul2(u64 a, u64 b) {
    u64 d; asm("mul.rn.f32x2 %0, %1, %2;" : "=l"(d) : "l"(a), "l"(b)); return d;
}
static __device__ __forceinline__ u64 add2(u64 a, u64 b) {
    u64 d; asm("add.rn.f32x2 %0, %1, %2;" : "=l"(d) : "l"(a), "l"(b)); return d;
}

static __device__ __forceinline__ unsigned cmprs(int4 a, int4 b) {
    unsigned r = 0;
    r |= (a.x != 0) ? 1u   : 0u;
    r |= (a.y != 0) ? 2u   : 0u;
    r |= (a.z != 0) ? 4u   : 0u;
    r |= (a.w != 0) ? 8u   : 0u;
    r |= (b.x != 0) ? 16u  : 0u;
    r |= (b.y != 0) ? 32u  : 0u;
    r |= (b.z != 0) ? 64u  : 0u;
    r |= (b.w != 0) ? 128u : 0u;
    return r;
}

__global__ void __launch_bounds__(THREADS) crf_fwd_kernel(
    const float* __restrict__ emissions,
    const int*   __restrict__ tags,
    const int*   __restrict__ mask,
    const float* __restrict__ trans,
    float*       __restrict__ out)
{
    __shared__ float s_traw[NTAGS * NTAGS];
    __shared__ __align__(16) float s_p[WPB][2][32];
    __shared__ int s_done;
    __shared__ float s_red[THREADS];

    const int tid  = threadIdx.x;
    const int lane = tid & 31;
    const int wid  = tid >> 5;
    const int b    = blockIdx.x * WPB + wid;

    for (int i = tid; i < NTAGS * NTAGS; i += THREADS) s_traw[i] = trans[i];
    __syncthreads();

    const bool act = (lane < NTAGS);
    const bool isg = (lane >= NTAGS);
    const int  gk  = lane - NTAGS;

    const float* em  = emissions + (size_t)b * (SEQ * NTAGS);
    const int*   tg  = tags + (size_t)b * SEQ;
    const int*   mkp = mask + (size_t)b * SEQ;

    // Early independent LDGs: masks + tags for chunk 0, raw emissions chunk 0.
    int4 ma0 = *(const int4*)(mkp);
    int4 mb0 = *(const int4*)(mkp + 4);
    int  tt  = isg ? tg[gk] : 0;

    float raw[CH];
#pragma unroll
    for (int k = 0; k < CH; k++)
        raw[k] = act ? em[k * NTAGS + lane] : -1e30f;

    // Packed expT columns; then normalize by R = max column sum.
    u64 tc[12];
#pragma unroll
    for (int k = 0; k < 12; k++) {
        float a = act ? __expf(trans[(2 * k)     * NTAGS + lane]) : 0.f;
        float c = act ? __expf(trans[(2 * k + 1) * NTAGS + lane]) : 0.f;
        tc[k] = pk2(a, c);
    }
    u64 cs2 = tc[0];
#pragma unroll
    for (int k = 1; k < 12; k++) cs2 = add2(cs2, tc[k]);
    float cl, chh; un2(cs2, cl, chh);
    float R = cl + chh;
#pragma unroll
    for (int o = 16; o; o >>= 1)
        R = fmaxf(R, __shfl_xor_sync(FULL, R, o));
    const float rinv = 1.0f / R;
    const float lnR  = __logf(R);
    const u64 rin2 = pk2(rinv, rinv);
#pragma unroll
    for (int k = 0; k < 12; k++) tc[k] = mul2(tc[k], rin2);

    unsigned mbits = cmprs(ma0, mb0);

    float expe[CH];
#pragma unroll
    for (int k = 0; k < CH; k++) expe[k] = __expf(raw[k]);

    // raw <- chunk 1
#pragma unroll
    for (int k = 0; k < CH; k++)
        raw[k] = act ? em[(CH + k) * NTAGS + lane] : -1e30f;

    // init: p = exp(e0 - m0) = expe[0]/max(expe[0]); C = log(max)
    float M = expe[0];
#pragma unroll
    for (int o = 16; o; o >>= 1)
        M = fmaxf(M, __shfl_xor_sync(FULL, M, o));
    float p  = act ? expe[0] * (1.0f / M) : 0.f;
    float Cc = __logf(M);

    int   tcarry = 0;
    float gold = 0.f, ge = 0.f;

#define STEP(EX, MT, RS)                                                      \
    do {                                                                      \
        float* _b = &s_p[wid][(k) & 1][0];                                    \
        _b[lane] = p;                                                         \
        __syncwarp();                                                         \
        const ulonglong2* _q = (const ulonglong2*)_b;                         \
        ulonglong2 q0 = _q[0], q1 = _q[1], q2 = _q[2];                        \
        u64 a0 = mul2(q0.x, tc[0]);                                           \
        u64 a1 = mul2(q0.y, tc[1]);                                           \
        u64 a2 = mul2(q1.x, tc[2]);                                           \
        u64 a3 = mul2(q1.y, tc[3]);                                           \
        a0 = fma2(q2.x, tc[4], a0);                                           \
        a1 = fma2(q2.y, tc[5], a1);                                           \
        ulonglong2 q3 = _q[3], q4 = _q[4], q5 = _q[5];                        \
        a2 = fma2(q3.x, tc[6], a2);                                           \
        a3 = fma2(q3.y, tc[7], a3);                                           \
        a0 = fma2(q4.x, tc[8], a0);                                           \
        a1 = fma2(q4.y, tc[9], a1);                                           \
        a2 = fma2(q5.x, tc[10], a2);                                          \
        a3 = fma2(q5.y, tc[11], a3);                                          \
        u64 _aa = add2(add2(a0, a1), add2(a2, a3));                           \
        float _sl, _sh; un2(_aa, _sl, _sh);                                   \
        const float _u = (_sl + _sh) * (EX);                                  \
        p = (MT) ? _u : p;                                                    \
        if (RS) {                                                             \
            float _m = p;                                                     \
            _Pragma("unroll")                                                 \
            for (int _o = 16; _o; _o >>= 1)                                   \
                _m = fmaxf(_m, __shfl_xor_sync(FULL, _m, _o));                \
            p *= (1.0f / _m);                                                 \
            Cc += npop * lnR + __logf(_m);                                    \
        }                                                                     \
    } while (0)

#define CBODY(K0, CM)                                                         \
    do {                                                                      \
        int4 na, nb; int tt_nx = 0;                                           \
        if (c + 1 < NCHUNK) {                                                 \
            na = *(const int4*)(mkp + (c + 1) * CH);                          \
            nb = *(const int4*)(mkp + (c + 1) * CH + 4);                      \
            tt_nx = isg ? tg[(c + 1) * CH + gk] : 0;                          \
        } else { na = make_int4(0,0,0,0); nb = na; }                          \
        if (isg) ge = em[(c * CH + gk) * NTAGS + tt];                         \
        const float npop = (float)__popc(mbits & (CM));                       \
        _Pragma("unroll")                                                     \
        for (int k = K0; k < CH; k++)                                         \
            STEP(expe[k], ((mbits >> k) & 1u), (k == 7));                     \
        int tp = __shfl_up_sync(FULL, tt, 1);                                 \
        if (gk == 0) tp = tcarry;                                             \
        if (isg && ((mbits >> gk) & 1u)) {                                    \
            float gt = (c == 0 && gk == 0) ? 0.f : s_traw[tp * NTAGS + tt];   \
            gold += ge + gt;                                                  \
        }                                                                     \
        tcarry = __shfl_sync(FULL, tt, 31);                                   \
        tt = tt_nx;                                                           \
        if (c + 1 < NCHUNK) {                                                 \
            _Pragma("unroll")                                                 \
            for (int k = 0; k < CH; k++) expe[k] = __expf(raw[k]);            \
        }                                                                     \
        if (c + 2 < NCHUNK) {                                                 \
            _Pragma("unroll")                                                 \
            for (int k = 0; k < CH; k++)                                      \
                raw[k] = act ? em[((c + 2) * CH + k) * NTAGS + lane] : -1e30f;\
        }                                                                     \
        mbits = cmprs(na, nb);                                                \
    } while (0)

    { const int c = 0; CBODY(1, 0xFEu); }   // k=0 consumed by init
    for (int c = 1; c < NCHUNK; c++) { CBODY(0, 0xFFu); }

    // log_den: p already normalized by the final chunk rescale.
    float zs = p;
#pragma unroll
    for (int o = 16; o; o >>= 1)
        zs += __shfl_xor_sync(FULL, zs, o);
    const float log_den = Cc + __logf(zs);

    gold += __shfl_xor_sync(FULL, gold, 1);
    gold += __shfl_xor_sync(FULL, gold, 2);
    gold += __shfl_xor_sync(FULL, gold, 4);
    const float gold_all = __shfl_sync(FULL, gold, NTAGS);

    if (lane == 0) g_part[b] = log_den - gold_all;

    __syncthreads();
    if (tid == 0) {
        __threadfence();
        unsigned prev = atomicInc(&g_ctr, gridDim.x - 1);
        s_done = (prev == gridDim.x - 1);
    }
    __syncthreads();
    if (s_done) {
        float v = 0.0f;
        for (int i = tid; i < BATCH; i += THREADS) v += g_part[i];
        s_red[tid] = v;
        __syncthreads();
#pragma unroll
        for (int s = THREADS / 2; s; s >>= 1) {
            if (tid < s) s_red[tid] += s_red[tid + s];
            __syncthreads();
        }
        if (tid == 0) out[0] = s_red[0] * (1.0f / BATCH);
    }
}

extern "C" void kernel_launch(void* const* d_in, const int* in_sizes, int n_in,
                              void* d_out, int out_size)
{
    const float* emissions = (const float*)d_in[0];
    const int*   tags      = (const int*)d_in[1];
    const int*   mask      = (const int*)d_in[2];
    const float* trans     = (const float*)d_in[3];

    crf_fwd_kernel<<<BATCH / WPB, THREADS>>>(
        emissions, tags, mask, trans, (float*)d_out);
}

// round 6
// speedup vs baseline: 1.2406x; 1.2406x over previous
#include <cuda_runtime.h>
#include <cstdint>

#define NTAGS 24
#define SEQ   512
#define BATCH 2048
#define WPB   4
#define THREADS (WPB * 32)
#define CH    8
#define NCHUNK (SEQ / CH)
#define FULL  0xffffffffu

typedef unsigned long long u64;

__device__ float    g_part[BATCH];
__device__ unsigned g_ctr = 0;

static __device__ __forceinline__ u64 pk2(float lo, float hi) {
    u64 r; asm("mov.b64 %0, {%1, %2};" : "=l"(r) : "f"(lo), "f"(hi)); return r;
}
static __device__ __forceinline__ void un2(u64 v, float& lo, float& hi) {
    asm("mov.b64 {%0, %1}, %2;" : "=f"(lo), "=f"(hi) : "l"(v));
}
static __device__ __forceinline__ u64 fma2(u64 a, u64 b, u64 c) {
    u64 d; asm("fma.rn.f32x2 %0, %1, %2, %3;" : "=l"(d) : "l"(a), "l"(b), "l"(c)); return d;
}
static __device__ __forceinline__ u64 mul2(u64 a, u64 b) {
    u64 d; asm("mul.rn.f32x2 %0, %1, %2;" : "=l"(d) : "l"(a), "l"(b)); return d;
}
static __device__ __forceinline__ u64 add2(u64 a, u64 b) {
    u64 d; asm("add.rn.f32x2 %0, %1, %2;" : "=l"(d) : "l"(a), "l"(b)); return d;
}
static __device__ __forceinline__ unsigned cmprs(int4 a, int4 b) {
    unsigned r = 0;
    r |= (a.x != 0) ? 1u   : 0u;  r |= (a.y != 0) ? 2u   : 0u;
    r |= (a.z != 0) ? 4u   : 0u;  r |= (a.w != 0) ? 8u   : 0u;
    r |= (b.x != 0) ? 16u  : 0u;  r |= (b.y != 0) ? 32u  : 0u;
    r |= (b.z != 0) ? 64u  : 0u;  r |= (b.w != 0) ? 128u : 0u;
    return r;
}

__global__ void __launch_bounds__(THREADS) crf_fwd_kernel(
    const float* __restrict__ emissions,
    const int*   __restrict__ tags,
    const int*   __restrict__ mask,
    const float* __restrict__ trans,
    float*       __restrict__ out)
{
    __shared__ float s_traw[NTAGS * NTAGS];
    __shared__ __align__(16) float s_p[WPB][2][32];
    __shared__ int s_done;
    __shared__ float s_red[THREADS];

    const int tid  = threadIdx.x;
    const int lane = tid & 31;
    const int wid  = tid >> 5;
    const int b    = blockIdx.x * WPB + wid;

    for (int i = tid; i < NTAGS * NTAGS; i += THREADS) s_traw[i] = trans[i];
    __syncthreads();

    const bool act = (lane < NTAGS);
    const bool isg = (lane >= NTAGS);
    const int  ggk = isg ? (lane - NTAGS) : 0;  // safe for all lanes

    const float* em  = emissions + (size_t)b * (SEQ * NTAGS);
    const int*   tg  = tags + (size_t)b * SEQ;
    const int*   mkp = mask + (size_t)b * SEQ;

#define PRE(C, EB)                                                            \
    do {                                                                      \
        const float* _ep = em + (size_t)(C) * (CH * NTAGS) + lane;            \
        _Pragma("unroll")                                                     \
        for (int _k = 0; _k < CH; _k++)                                       \
            EB[_k] = act ? _ep[_k * NTAGS] : -1e30f;                          \
    } while (0)

    // early loads: masks + tags chunk 0, raw emissions chunks 0 & 1
    int4 ma0 = *(const int4*)(mkp);
    int4 mb0 = *(const int4*)(mkp + 4);
    int  tt  = tg[ggk];

    float eb0[CH], eb1[CH];
    PRE(0, eb0);
    PRE(1, eb1);

    // packed expT columns, normalized by R = max column sum
    u64 tc[12];
#pragma unroll
    for (int k = 0; k < 12; k++) {
        float a = act ? __expf(trans[(2 * k)     * NTAGS + lane]) : 0.f;
        float c = act ? __expf(trans[(2 * k + 1) * NTAGS + lane]) : 0.f;
        tc[k] = pk2(a, c);
    }
    u64 cs2 = tc[0];
#pragma unroll
    for (int k = 1; k < 12; k++) cs2 = add2(cs2, tc[k]);
    float cl, chh; un2(cs2, cl, chh);
    float R = cl + chh;
#pragma unroll
    for (int o = 16; o; o >>= 1)
        R = fmaxf(R, __shfl_xor_sync(FULL, R, o));
    const float lnR = __logf(R);
    const u64 rin2 = pk2(1.0f / R, 1.0f / R);
#pragma unroll
    for (int k = 0; k < 12; k++) tc[k] = mul2(tc[k], rin2);

    unsigned mbits = cmprs(ma0, mb0);
    int ntot = __popc(mbits & 0xFEu);   // t=0 is not a transition step

    float expe[CH];
#pragma unroll
    for (int k = 0; k < CH; k++) expe[k] = __expf(eb0[k]);  // exp(-1e30)=0 for idle lanes

    // init: p = expe[0]/max, C = log(max)
    float M = expe[0];
#pragma unroll
    for (int o = 16; o; o >>= 1)
        M = fmaxf(M, __shfl_xor_sync(FULL, M, o));
    float p  = expe[0] * __fdividef(1.0f, M);
    float Cc = __logf(M);

    int   tcarry = 0;
    float gold = 0.f;

    // matvec core: no warpsync — convergent warp, in-order LSU, compiler barrier
#define MATV(K, EX, UOUT)                                                     \
    float* _b = &s_p[wid][(K) & 1][0];                                        \
    _b[lane] = p;                                                             \
    asm volatile("" ::: "memory");                                            \
    const ulonglong2* _q = (const ulonglong2*)_b;                             \
    ulonglong2 _q0 = _q[0], _q1 = _q[1], _q2 = _q[2];                         \
    u64 _a0 = mul2(_q0.x, tc[0]);                                             \
    u64 _a1 = mul2(_q0.y, tc[1]);                                             \
    u64 _a2 = mul2(_q1.x, tc[2]);                                             \
    u64 _a3 = mul2(_q1.y, tc[3]);                                             \
    _a0 = fma2(_q2.x, tc[4], _a0);                                            \
    _a1 = fma2(_q2.y, tc[5], _a1);                                            \
    ulonglong2 _q3 = _q[3], _q4 = _q[4], _q5 = _q[5];                         \
    _a2 = fma2(_q3.x, tc[6], _a2);                                            \
    _a3 = fma2(_q3.y, tc[7], _a3);                                            \
    _a0 = fma2(_q4.x, tc[8], _a0);                                            \
    _a1 = fma2(_q4.y, tc[9], _a1);                                            \
    _a2 = fma2(_q5.x, tc[10], _a2);                                           \
    _a3 = fma2(_q5.y, tc[11], _a3);                                           \
    u64 _s2 = add2(add2(_a0, _a1), add2(_a2, _a3));                           \
    float _sl, _sh; un2(_s2, _sl, _sh);                                       \
    const float UOUT = (_sl + _sh) * (EX);

#define RESCALE()                                                             \
    do {                                                                      \
        float _m = p;                                                         \
        _Pragma("unroll")                                                     \
        for (int _o = 16; _o; _o >>= 1)                                       \
            _m = fmaxf(_m, __shfl_xor_sync(FULL, _m, _o));                    \
        p *= __fdividef(1.0f, _m);                                            \
        Cc += __logf(_m);                                                     \
    } while (0)

#define CBODY(C, K0, EBPRE, EBCONV, PRE_ON, NXT_ON, RSFLAG, FIRST)            \
    do {                                                                      \
        const float ge = em[((C) * CH + ggk) * NTAGS + tt];                   \
        int tt_nx = 0;                                                        \
        int4 _na = make_int4(0, 0, 0, 0), _nb = _na;                          \
        if (NXT_ON) {                                                         \
            tt_nx = tg[((C) + 1) * CH + ggk];                                 \
            _na = *(const int4*)(mkp + ((C) + 1) * CH);                       \
            _nb = *(const int4*)(mkp + ((C) + 1) * CH + 4);                   \
        }                                                                     \
        if (PRE_ON) { PRE((C) + 2, EBPRE); }                                  \
        if (mbits == 0xFFu) {                                                 \
            _Pragma("unroll")                                                 \
            for (int k = K0; k < CH; k++) { MATV(k, expe[k], _u); p = _u; }   \
        } else {                                                              \
            _Pragma("unroll")                                                 \
            for (int k = K0; k < CH; k++) {                                   \
                MATV(k, expe[k], _u);                                         \
                p = ((mbits >> k) & 1u) ? _u : p;                             \
            }                                                                 \
        }                                                                     \
        int _tp = __shfl_up_sync(FULL, tt, 1);                                \
        _tp = (lane == NTAGS) ? tcarry : _tp;                                 \
        float _gt = s_traw[_tp * NTAGS + tt];                                 \
        if (FIRST) _gt = (lane == NTAGS) ? 0.f : _gt;                         \
        const unsigned _gs = (mbits >> ggk) & 1u;                             \
        gold += (isg && _gs) ? (ge + _gt) : 0.f;                              \
        tcarry = __shfl_sync(FULL, tt, 31);                                   \
        tt = tt_nx;                                                           \
        if (RSFLAG) RESCALE();                                                \
        if (NXT_ON) {                                                         \
            _Pragma("unroll")                                                 \
            for (int k = 0; k < CH; k++) expe[k] = __expf(EBCONV[k]);         \
            mbits = cmprs(_na, _nb);                                          \
            ntot += __popc(mbits);                                            \
        }                                                                     \
    } while (0)

    // chunk 0 (k starts at 1; PRE -> eb0, convert eb1)
    CBODY(0, 1, eb0, eb1, true, true, false, true);

    // chunks 1..60 in parity pairs (odd: PRE->eb1/conv eb0; even: PRE->eb0/conv eb1)
    for (int c = 1; c <= 59; c += 2) {
        CBODY(c,     0, eb1, eb0, true, true, ((c & 3) == 3), false);
        CBODY(c + 1, 0, eb0, eb1, true, true, false,          false);
    }

    // tail: 61 (PRE(63) ok), 62 (no PRE), 63 (no PRE, no next, final rescale)
    CBODY(61, 0, eb1, eb0, true,  true,  false, false);
    CBODY(62, 0, eb0, eb1, false, true,  false, false);
    CBODY(63, 0, eb1, eb0, false, false, true,  false);

    // log_den: p normalized by the c=63 rescale
    float zs = p;
#pragma unroll
    for (int o = 16; o; o >>= 1)
        zs += __shfl_xor_sync(FULL, zs, o);
    const float log_den = Cc + (float)ntot * lnR + __logf(zs);

    gold += __shfl_xor_sync(FULL, gold, 1);
    gold += __shfl_xor_sync(FULL, gold, 2);
    gold += __shfl_xor_sync(FULL, gold, 4);
    const float gold_all = __shfl_sync(FULL, gold, NTAGS);

    if (lane == 0) g_part[b] = log_den - gold_all;

    // fused deterministic reduction
    __syncthreads();
    if (tid == 0) {
        __threadfence();
        unsigned prev = atomicInc(&g_ctr, gridDim.x - 1);
        s_done = (prev == gridDim.x - 1);
    }
    __syncthreads();
    if (s_done) {
        float v = 0.0f;
        for (int i = tid; i < BATCH; i += THREADS) v += g_part[i];
        s_red[tid] = v;
        __syncthreads();
#pragma unroll
        for (int s = THREADS / 2; s; s >>= 1) {
            if (tid < s) s_red[tid] += s_red[tid + s];
            __syncthreads();
        }
        if (tid == 0) out[0] = s_red[0] * (1.0f / BATCH);
    }
}

extern "C" void kernel_launch(void* const* d_in, const int* in_sizes, int n_in,
                              void* d_out, int out_size)
{
    const float* emissions = (const float*)d_in[0];
    const int*   tags      = (const int*)d_in[1];
    const int*   mask      = (const int*)d_in[2];
    const float* trans     = (const float*)d_in[3];

    crf_fwd_kernel<<<BATCH / WPB, THREADS>>>(
        emissions, tags, mask, trans, (float*)d_out);
}